// round 6
// baseline (speedup 1.0000x reference)
#include <cuda_runtime.h>
#include <math.h>

#define NMAX 50000
#define EMAX 600000
#define HDIM 128
#define NHEADS 4
#define GMAX 64

// ---------------- scratch (device globals; no allocation) ----------------
__device__ float d_h[NMAX * HDIM];
__device__ float d_feat[NMAX * HDIM];
__device__ float d_el[NMAX * NHEADS];
__device__ float d_er[NMAX * NHEADS];
__device__ float d_elmax[3 * NHEADS];      // per-layer, per-head global max of el
__device__ int   d_deg[NMAX];
__device__ int   d_cur[NMAX];
__device__ int   d_offs[NMAX + 1];
__device__ int   d_esrc[EMAX];
__device__ int   d_bsum[64];
__device__ int   d_bbase[64];
__device__ float d_gate[NMAX];
__device__ float d_gmax[GMAX];
__device__ float d_gz[GMAX];
__device__ float d_zg[GMAX * HDIM];
__device__ float d_z1[GMAX * HDIM];

// ---------------- helpers ----------------
__device__ __forceinline__ void atomicMaxFloat(float* addr, float v) {
    if (v >= 0.0f) atomicMax((int*)addr, __float_as_int(v));
    else           atomicMin((unsigned int*)addr, __float_as_uint(v));
}

__device__ __forceinline__ void redAdd4(float* p, float a, float b, float c, float d) {
    asm volatile("red.global.add.v4.f32 [%0], {%1, %2, %3, %4};"
                 :: "l"(p), "f"(a), "f"(b), "f"(c), "f"(d) : "memory");
}

__device__ __forceinline__ float warpSum(float v) {
    #pragma unroll
    for (int o = 16; o > 0; o >>= 1) v += __shfl_xor_sync(0xffffffffu, v, o);
    return v;
}

// ---------------- kernels ----------------

// h = gate_emb[gate_types] + qubit_emb[qubit_indices]
__global__ void embed_k(const int* __restrict__ gt, const int* __restrict__ qi,
                        const float* __restrict__ ge, const float* __restrict__ qe, int n) {
    int i = blockIdx.x * blockDim.x + threadIdx.x;
    if (i >= n * (HDIM / 4)) return;
    int node = i >> 5;
    int c = (i & 31) << 2;
    int g = gt[node], q = qi[node];
    float4 a = *(const float4*)(ge + g * HDIM + c);
    float4 b = *(const float4*)(qe + q * HDIM + c);
    float4 r;
    r.x = a.x + b.x; r.y = a.y + b.y; r.z = a.z + b.z; r.w = a.w + b.w;
    *(float4*)(d_h + node * HDIM + c) = r;
}

// --------- CSR build (once per call) ---------
__global__ void csr_zero_k(int n) {
    int i = blockIdx.x * blockDim.x + threadIdx.x;
    if (i < n) { d_deg[i] = 0; d_cur[i] = 0; }
    if (i < 3 * NHEADS) d_elmax[i] = -1e30f;
}

__global__ void csr_hist_k(const int* __restrict__ dst, int e) {
    int i = blockIdx.x * blockDim.x + threadIdx.x;
    if (i < e) atomicAdd(&d_deg[dst[i]], 1);
}

// phase 1: per-block (1024 elems) exclusive scan; block total -> d_bsum
__global__ void csr_scan1_k(int n) {
    __shared__ int wsum[32];
    int i = blockIdx.x * 1024 + threadIdx.x;
    int lane = threadIdx.x & 31, wid = threadIdx.x >> 5;
    int v = (i < n) ? d_deg[i] : 0;
    int x = v;
    #pragma unroll
    for (int o = 1; o < 32; o <<= 1) {
        int t = __shfl_up_sync(0xffffffffu, x, o);
        if (lane >= o) x += t;
    }
    if (lane == 31) wsum[wid] = x;
    __syncthreads();
    if (wid == 0) {
        int y = wsum[lane];
        #pragma unroll
        for (int o = 1; o < 32; o <<= 1) {
            int t = __shfl_up_sync(0xffffffffu, y, o);
            if (lane >= o) y += t;
        }
        wsum[lane] = y;
    }
    __syncthreads();
    int base = (wid > 0) ? wsum[wid - 1] : 0;
    if (i < n) d_offs[i] = base + x - v;
    if (threadIdx.x == 1023) d_bsum[blockIdx.x] = wsum[31];
}

// phase 2: one warp scans <=64 block sums exclusively; writes total to d_offs[n]
__global__ void csr_scan2_k(int nb, int n) {
    int lane = threadIdx.x;
    int v0 = (lane < nb) ? d_bsum[lane] : 0;
    int v1 = (32 + lane < nb) ? d_bsum[32 + lane] : 0;
    int x0 = v0, x1 = v1;
    #pragma unroll
    for (int o = 1; o < 32; o <<= 1) {
        int t0 = __shfl_up_sync(0xffffffffu, x0, o);
        int t1 = __shfl_up_sync(0xffffffffu, x1, o);
        if (lane >= o) { x0 += t0; x1 += t1; }
    }
    int tot0 = __shfl_sync(0xffffffffu, x0, 31);
    int tot1 = __shfl_sync(0xffffffffu, x1, 31);
    if (lane < nb) d_bbase[lane] = x0 - v0;
    if (32 + lane < nb) d_bbase[32 + lane] = tot0 + x1 - v1;
    if (lane == 0) d_offs[n] = tot0 + tot1;
}

// phase 3: add block bases
__global__ void csr_scan3_k(int n) {
    int i = blockIdx.x * 1024 + threadIdx.x;
    if (i < n) d_offs[i] += d_bbase[blockIdx.x];
}

__global__ void csr_scatter_k(const int* __restrict__ src, const int* __restrict__ dst, int e) {
    int i = blockIdx.x * blockDim.x + threadIdx.x;
    if (i >= e) return;
    int d = dst[i];
    int pos = d_offs[d] + atomicAdd(&d_cur[d], 1);
    d_esrc[pos] = src[i];
}

// feat = h @ W[l] with fused attn epilogue (el/er from accumulator registers)
// and per-head global el-max accumulation into d_elmax[l*4+h].
__global__ void gemm_attn_k(const float* __restrict__ B,
                            const float* __restrict__ al, const float* __restrict__ ar,
                            int n, int l) {
    __shared__ float Ast[HDIM][68];
    __shared__ float smax[NHEADS];
    int row0 = blockIdx.x * 64;
    int tid = threadIdx.x;
    if (tid < NHEADS) smax[tid] = -1e30f;
    // stage A transposed: float4 coalesced loads, 4 scalar STS (2-way conflict)
    #pragma unroll
    for (int it = 0; it < 8; it++) {
        int idx4 = tid + it * 256;             // element-group index
        int r = idx4 >> 5;                     // 0..63
        int c = (idx4 & 31) * 4;               // 0..124
        float4 v = make_float4(0.f, 0.f, 0.f, 0.f);
        if (row0 + r < n) v = *(const float4*)(d_h + (row0 + r) * HDIM + c);
        Ast[c][r] = v.x; Ast[c + 1][r] = v.y; Ast[c + 2][r] = v.z; Ast[c + 3][r] = v.w;
    }
    __syncthreads();
    int wid = tid >> 5, lane = tid & 31;
    int rbase = wid * 8;
    int col = lane * 4;
    int head = lane >> 3;
    float acc[8][4];
    #pragma unroll
    for (int r = 0; r < 8; r++)
        #pragma unroll
        for (int c = 0; c < 4; c++) acc[r][c] = 0.0f;
    #pragma unroll 8
    for (int k = 0; k < HDIM; k++) {
        float4 a0 = *(const float4*)&Ast[k][rbase];
        float4 a1 = *(const float4*)&Ast[k][rbase + 4];
        float4 b = __ldg((const float4*)(B + k * HDIM + col));
        float arr[8] = {a0.x, a0.y, a0.z, a0.w, a1.x, a1.y, a1.z, a1.w};
        #pragma unroll
        for (int r = 0; r < 8; r++) {
            acc[r][0] += arr[r] * b.x;
            acc[r][1] += arr[r] * b.y;
            acc[r][2] += arr[r] * b.z;
            acc[r][3] += arr[r] * b.w;
        }
    }
    float4 av = __ldg((const float4*)(al + col));
    float4 rv = __ldg((const float4*)(ar + col));
    float myelmax = -1e30f;
    #pragma unroll
    for (int r = 0; r < 8; r++) {
        int row = row0 + rbase + r;
        if (row < n) {
            float4 o = make_float4(acc[r][0], acc[r][1], acc[r][2], acc[r][3]);
            *(float4*)(d_feat + row * HDIM + col) = o;
        }
        float sl = acc[r][0] * av.x + acc[r][1] * av.y + acc[r][2] * av.z + acc[r][3] * av.w;
        float sr = acc[r][0] * rv.x + acc[r][1] * rv.y + acc[r][2] * rv.z + acc[r][3] * rv.w;
        #pragma unroll
        for (int o = 4; o > 0; o >>= 1) {
            sl += __shfl_xor_sync(0xffffffffu, sl, o);
            sr += __shfl_xor_sync(0xffffffffu, sr, o);
        }
        if ((lane & 7) == 0 && row < n) {
            d_el[row * NHEADS + head] = sl;
            d_er[row * NHEADS + head] = sr;
            myelmax = fmaxf(myelmax, sl);
        }
    }
    if ((lane & 7) == 0) atomicMaxFloat(&smax[head], myelmax);
    __syncthreads();
    if (tid < NHEADS) atomicMaxFloat(&d_elmax[l * NHEADS + tid], smax[tid]);
}

// Fused per-layer GAT aggregation: warp per dst node. Single edge pass:
// m_h = leaky(global_el_max_h + er_h) is a valid softmax shift (monotone bound).
__global__ void gat_fused_k(const float* __restrict__ bias, int n, int l) {
    __shared__ float sh_a[8][128];   // per warp: 32 edges x 4 heads
    int warp = (blockIdx.x * blockDim.x + threadIdx.x) >> 5;
    if (warp >= n) return;
    int w = threadIdx.x >> 5;
    int lane = threadIdx.x & 31;
    int node = warp;
    int rs = d_offs[node], re = d_offs[node + 1];
    int head = lane >> 3;

    float4 er4 = *(const float4*)(d_er + node * NHEADS);
    float4 em = *(const float4*)(d_elmax + l * NHEADS);
    // per-head shift: leaky(elmax + er)  (upper bound of edge max, monotone)
    float m[4];
    {
        float t0 = em.x + er4.x; m[0] = (t0 > 0.0f) ? t0 : 0.2f * t0;
        float t1 = em.y + er4.y; m[1] = (t1 > 0.0f) ? t1 : 0.2f * t1;
        float t2 = em.z + er4.z; m[2] = (t2 > 0.0f) ? t2 : 0.2f * t2;
        float t3 = em.w + er4.w; m[3] = (t3 > 0.0f) ? t3 : 0.2f * t3;
    }

    float4 zacc = make_float4(0.0f, 0.0f, 0.0f, 0.0f);
    float4 acc = make_float4(0.0f, 0.0f, 0.0f, 0.0f);
    for (int base = rs; base < re; base += 32) {
        int i = base + lane;
        int s_reg = 0;
        float4 a4 = make_float4(0.0f, 0.0f, 0.0f, 0.0f);
        if (i < re) {
            s_reg = d_esrc[i];
            float4 el4 = *(const float4*)(d_el + s_reg * NHEADS);
            float v0 = el4.x + er4.x; v0 = (v0 > 0.0f) ? v0 : 0.2f * v0;
            float v1 = el4.y + er4.y; v1 = (v1 > 0.0f) ? v1 : 0.2f * v1;
            float v2 = el4.z + er4.z; v2 = (v2 > 0.0f) ? v2 : 0.2f * v2;
            float v3 = el4.w + er4.w; v3 = (v3 > 0.0f) ? v3 : 0.2f * v3;
            a4.x = __expf(v0 - m[0]); a4.y = __expf(v1 - m[1]);
            a4.z = __expf(v2 - m[2]); a4.w = __expf(v3 - m[3]);
            zacc.x += a4.x; zacc.y += a4.y; zacc.z += a4.z; zacc.w += a4.w;
        }
        *(float4*)&sh_a[w][lane * 4] = a4;
        __syncwarp();
        int cnt = min(32, re - base);
        #pragma unroll 4
        for (int j = 0; j < cnt; j++) {
            int s = __shfl_sync(0xffffffffu, s_reg, j);
            float a = sh_a[w][j * 4 + head];
            float4 f = *(const float4*)(d_feat + s * HDIM + lane * 4);
            acc.x += a * f.x; acc.y += a * f.y; acc.z += a * f.z; acc.w += a * f.w;
        }
        __syncwarp();
    }
    // reduce z across warp
    #pragma unroll
    for (int o = 16; o > 0; o >>= 1) {
        zacc.x += __shfl_xor_sync(0xffffffffu, zacc.x, o);
        zacc.y += __shfl_xor_sync(0xffffffffu, zacc.y, o);
        zacc.z += __shfl_xor_sync(0xffffffffu, zacc.z, o);
        zacc.w += __shfl_xor_sync(0xffffffffu, zacc.w, o);
    }
    float zh[4] = {zacc.x, zacc.y, zacc.z, zacc.w};
    float zq = zh[head];
    float rz = (zq > 0.0f) ? (1.0f / zq) : 0.0f;

    float4 hv = *(const float4*)(d_h + node * HDIM + lane * 4);
    float4 bv = *(const float4*)(bias + lane * 4);
    float4 y;
    y.x = fmaxf(acc.x * rz + hv.x + bv.x, 0.0f);
    y.y = fmaxf(acc.y * rz + hv.y + bv.y, 0.0f);
    y.z = fmaxf(acc.z * rz + hv.z + bv.z, 0.0f);
    y.w = fmaxf(acc.w * rz + hv.w + bv.w, 0.0f);
    *(float4*)(d_h + node * HDIM + lane * 4) = y;
}

// Fused LayerNorm + gate projection + per-graph gate max.
__global__ void ln_gate_k(const float* __restrict__ gamma, const float* __restrict__ beta,
                          const float* __restrict__ gw, const float* __restrict__ gb,
                          const int* __restrict__ gid, int n) {
    int t = blockIdx.x * blockDim.x + threadIdx.x;
    int node = t >> 5;
    if (node >= n) return;
    int lane = t & 31;
    float4 x = *(const float4*)(d_h + node * HDIM + lane * 4);
    float s = x.x + x.y + x.z + x.w;
    float sq = x.x * x.x + x.y * x.y + x.z * x.z + x.w * x.w;
    s = warpSum(s);
    sq = warpSum(sq);
    float mu = s * (1.0f / HDIM);
    float var = sq * (1.0f / HDIM) - mu * mu;
    float inv = rsqrtf(var + 1e-5f);
    float4 g = *(const float4*)(gamma + lane * 4);
    float4 b = *(const float4*)(beta + lane * 4);
    float4 y;
    y.x = (x.x - mu) * inv * g.x + b.x;
    y.y = (x.y - mu) * inv * g.y + b.y;
    y.z = (x.z - mu) * inv * g.z + b.z;
    y.w = (x.w - mu) * inv * g.w + b.w;
    *(float4*)(d_h + node * HDIM + lane * 4) = y;
    float4 w = *(const float4*)(gw + lane * 4);
    float gp = y.x * w.x + y.y * w.y + y.z * w.z + y.w * w.w;
    gp = warpSum(gp);
    if (lane == 0) {
        float gv = gp + gb[0];
        d_gate[node] = gv;
        atomicMaxFloat(&d_gmax[gid[node]], gv);
    }
}

__global__ void pool_init_k() {
    int i = blockIdx.x * blockDim.x + threadIdx.x;
    if (i < GMAX * HDIM) d_zg[i] = 0.0f;
    if (i < GMAX) { d_gmax[i] = -INFINITY; d_gz[i] = 0.0f; }
}

// pool: p = exp(gate - gmax); gz += p; zg += p*h. One warp per node.
__global__ void pool_k(const int* __restrict__ gid, int n) {
    int t = blockIdx.x * blockDim.x + threadIdx.x;
    int node = t >> 5;
    if (node >= n) return;
    int lane = t & 31;
    int g = gid[node];
    float p = __expf(d_gate[node] - d_gmax[g]);
    if (lane == 0) atomicAdd(&d_gz[g], p);
    float4 x = *(const float4*)(d_h + node * HDIM + lane * 4);
    redAdd4(d_zg + g * HDIM + lane * 4, x.x * p, x.y * p, x.z * p, x.w * p);
}

// z1 = relu((zg/gz) @ proj_w1 + b1)
__global__ void final1_k(const float* __restrict__ W1, const float* __restrict__ b1) {
    __shared__ float row[HDIM];
    int g = blockIdx.x;
    int t = threadIdx.x;
    float gz = d_gz[g];
    float inv = (gz > 0.0f) ? (1.0f / gz) : 0.0f;
    row[t] = d_zg[g * HDIM + t] * inv;
    __syncthreads();
    float acc = b1[t];
    #pragma unroll 8
    for (int k = 0; k < HDIM; k++) acc += row[k] * W1[k * HDIM + t];
    d_z1[g * HDIM + t] = (acc > 0.0f) ? acc : 0.0f;
}

// out = z1 @ proj_w2 + b2
__global__ void final2_k(const float* __restrict__ W2, const float* __restrict__ b2,
                         float* __restrict__ out) {
    __shared__ float row[HDIM];
    int g = blockIdx.x;
    int t = threadIdx.x;
    row[t] = d_z1[g * HDIM + t];
    row[t + 64] = d_z1[g * HDIM + t + 64];
    __syncthreads();
    float acc = b2[t];
    #pragma unroll 8
    for (int k = 0; k < HDIM; k++) acc += row[k] * W2[k * 64 + t];
    out[g * 64 + t] = acc;
}

// ---------------- launch ----------------
extern "C" void kernel_launch(void* const* d_in, const int* in_sizes, int n_in,
                              void* d_out, int out_size) {
    const int*   gt    = (const int*)d_in[0];
    const int*   qi    = (const int*)d_in[1];
    const int*   src   = (const int*)d_in[2];
    const int*   dst   = (const int*)d_in[3];
    const int*   gid   = (const int*)d_in[4];
    const float* ge    = (const float*)d_in[5];
    const float* qe    = (const float*)d_in[6];
    const float* W     = (const float*)d_in[7];
    const float* al    = (const float*)d_in[8];
    const float* ar    = (const float*)d_in[9];
    const float* bias  = (const float*)d_in[10];
    const float* gamma = (const float*)d_in[11];
    const float* beta  = (const float*)d_in[12];
    const float* gw    = (const float*)d_in[13];
    const float* gb    = (const float*)d_in[14];
    const float* W1    = (const float*)d_in[15];
    const float* b1    = (const float*)d_in[16];
    const float* W2    = (const float*)d_in[17];
    const float* b2    = (const float*)d_in[18];

    int n = in_sizes[0];
    int e = in_sizes[2];

    const int T = 256;
    int gEmbed = (n * (HDIM / 4) + T - 1) / T;
    int gGemm  = (n + 63) / 64;
    int gWarpN = (n * 32 + T - 1) / T;
    int gEdge  = (e + T - 1) / T;
    int gNode  = (n + T - 1) / T;
    int nb     = (n + 1023) / 1024;

    embed_k<<<gEmbed, T>>>(gt, qi, ge, qe, n);

    csr_zero_k<<<gNode, T>>>(n);
    csr_hist_k<<<gEdge, T>>>(dst, e);
    csr_scan1_k<<<nb, 1024>>>(n);
    csr_scan2_k<<<1, 32>>>(nb, n);
    csr_scan3_k<<<nb, 1024>>>(n);
    csr_scatter_k<<<gEdge, T>>>(src, dst, e);

    for (int l = 0; l < 3; l++) {
        gemm_attn_k<<<gGemm, 256>>>(W + l * HDIM * HDIM, al + l * HDIM, ar + l * HDIM, n, l);
        gat_fused_k<<<gWarpN, T>>>(bias + l * HDIM, n, l);
    }

    pool_init_k<<<(GMAX * HDIM + T - 1) / T, T>>>();
    ln_gate_k<<<gWarpN, T>>>(gamma, beta, gw, gb, gid, n);
    pool_k<<<gWarpN, T>>>(gid, n);
    final1_k<<<GMAX, HDIM>>>(W1, b1);
    final2_k<<<GMAX, 64>>>(W2, b2, (float*)d_out);
}

// round 7
// speedup vs baseline: 1.0214x; 1.0214x over previous
#include <cuda_runtime.h>
#include <math.h>

#define NMAX 50000
#define EMAX 600000
#define HDIM 128
#define NHEADS 4
#define GMAX 64

// ---------------- scratch (device globals; no allocation) ----------------
__device__ float d_h[NMAX * HDIM];
__device__ float d_feat[NMAX * HDIM];
__device__ float d_el[NMAX * NHEADS];
__device__ float d_er[NMAX * NHEADS];
__device__ float d_elmax[3 * NHEADS];      // per-layer, per-head global max of el
__device__ int   d_deg[NMAX];
__device__ int   d_cur[NMAX];
__device__ int   d_offs[NMAX + 1];
__device__ int   d_esrc[EMAX];
__device__ int   d_bsum[64];
__device__ int   d_bbase[64];
__device__ float d_gate[NMAX];
__device__ float d_gmax[GMAX];
__device__ float d_gz[GMAX];
__device__ float d_zg[GMAX * HDIM];
__device__ float d_z1[GMAX * HDIM];

// ---------------- helpers ----------------
__device__ __forceinline__ void atomicMaxFloat(float* addr, float v) {
    if (v >= 0.0f) atomicMax((int*)addr, __float_as_int(v));
    else           atomicMin((unsigned int*)addr, __float_as_uint(v));
}

__device__ __forceinline__ void redAdd4(float* p, float a, float b, float c, float d) {
    asm volatile("red.global.add.v4.f32 [%0], {%1, %2, %3, %4};"
                 :: "l"(p), "f"(a), "f"(b), "f"(c), "f"(d) : "memory");
}

__device__ __forceinline__ float warpSum(float v) {
    #pragma unroll
    for (int o = 16; o > 0; o >>= 1) v += __shfl_xor_sync(0xffffffffu, v, o);
    return v;
}

// packed fp32x2 FMA (Blackwell): d = a*b + d elementwise on 2-lane packs
#define FMA2(d, a, b) asm("fma.rn.f32x2 %0, %1, %2, %0;" : "+l"(d) : "l"(a), "l"(b))
#define PACK_DUP(d, x) asm("mov.b64 %0, {%1, %1};" : "=l"(d) : "r"(__float_as_uint(x)))
#define UNPACK2(lo, hi, v) asm("mov.b64 {%0, %1}, %2;" : "=r"(lo), "=r"(hi) : "l"(v))

// ---------------- kernels ----------------

// h = gate_emb[gate_types] + qubit_emb[qubit_indices]
__global__ void embed_k(const int* __restrict__ gt, const int* __restrict__ qi,
                        const float* __restrict__ ge, const float* __restrict__ qe, int n) {
    int i = blockIdx.x * blockDim.x + threadIdx.x;
    if (i >= n * (HDIM / 4)) return;
    int node = i >> 5;
    int c = (i & 31) << 2;
    int g = gt[node], q = qi[node];
    float4 a = *(const float4*)(ge + g * HDIM + c);
    float4 b = *(const float4*)(qe + q * HDIM + c);
    float4 r;
    r.x = a.x + b.x; r.y = a.y + b.y; r.z = a.z + b.z; r.w = a.w + b.w;
    *(float4*)(d_h + node * HDIM + c) = r;
}

// --------- CSR build (once per call) ---------
__global__ void csr_zero_k(int n) {
    int i = blockIdx.x * blockDim.x + threadIdx.x;
    if (i < n) { d_deg[i] = 0; d_cur[i] = 0; }
    if (i < 3 * NHEADS) d_elmax[i] = -1e30f;
}

__global__ void csr_hist_k(const int* __restrict__ dst, int e) {
    int i = blockIdx.x * blockDim.x + threadIdx.x;
    if (i < e) atomicAdd(&d_deg[dst[i]], 1);
}

// phase 1: per-block (1024 elems) exclusive scan; block total -> d_bsum
__global__ void csr_scan1_k(int n) {
    __shared__ int wsum[32];
    int i = blockIdx.x * 1024 + threadIdx.x;
    int lane = threadIdx.x & 31, wid = threadIdx.x >> 5;
    int v = (i < n) ? d_deg[i] : 0;
    int x = v;
    #pragma unroll
    for (int o = 1; o < 32; o <<= 1) {
        int t = __shfl_up_sync(0xffffffffu, x, o);
        if (lane >= o) x += t;
    }
    if (lane == 31) wsum[wid] = x;
    __syncthreads();
    if (wid == 0) {
        int y = wsum[lane];
        #pragma unroll
        for (int o = 1; o < 32; o <<= 1) {
            int t = __shfl_up_sync(0xffffffffu, y, o);
            if (lane >= o) y += t;
        }
        wsum[lane] = y;
    }
    __syncthreads();
    int base = (wid > 0) ? wsum[wid - 1] : 0;
    if (i < n) d_offs[i] = base + x - v;
    if (threadIdx.x == 1023) d_bsum[blockIdx.x] = wsum[31];
}

// phase 2: one warp scans <=64 block sums exclusively; writes total to d_offs[n]
__global__ void csr_scan2_k(int nb, int n) {
    int lane = threadIdx.x;
    int v0 = (lane < nb) ? d_bsum[lane] : 0;
    int v1 = (32 + lane < nb) ? d_bsum[32 + lane] : 0;
    int x0 = v0, x1 = v1;
    #pragma unroll
    for (int o = 1; o < 32; o <<= 1) {
        int t0 = __shfl_up_sync(0xffffffffu, x0, o);
        int t1 = __shfl_up_sync(0xffffffffu, x1, o);
        if (lane >= o) { x0 += t0; x1 += t1; }
    }
    int tot0 = __shfl_sync(0xffffffffu, x0, 31);
    int tot1 = __shfl_sync(0xffffffffu, x1, 31);
    if (lane < nb) d_bbase[lane] = x0 - v0;
    if (32 + lane < nb) d_bbase[32 + lane] = tot0 + x1 - v1;
    if (lane == 0) d_offs[n] = tot0 + tot1;
}

// phase 3: add block bases
__global__ void csr_scan3_k(int n) {
    int i = blockIdx.x * 1024 + threadIdx.x;
    if (i < n) d_offs[i] += d_bbase[blockIdx.x];
}

__global__ void csr_scatter_k(const int* __restrict__ src, const int* __restrict__ dst, int e) {
    int i = blockIdx.x * blockDim.x + threadIdx.x;
    if (i >= e) return;
    int d = dst[i];
    int pos = d_offs[d] + atomicAdd(&d_cur[d], 1);
    d_esrc[pos] = src[i];
}

// feat = h @ W[l] with fused attn epilogue + per-head global el-max.
// Inner loop uses packed fp32x2 FMA: accumulators pair adjacent ROWS, A row-pairs
// come directly from transposed shared (64-bit LDS), B cols dup-packed per k.
__global__ void gemm_attn_k(const float* __restrict__ B,
                            const float* __restrict__ al, const float* __restrict__ ar,
                            int n, int l) {
    __shared__ float Ast[HDIM][68];
    __shared__ float smax[NHEADS];
    int row0 = blockIdx.x * 64;
    int tid = threadIdx.x;
    if (tid < NHEADS) smax[tid] = -1e30f;
    // stage A transposed: float4 coalesced loads, 4 scalar STS
    #pragma unroll
    for (int it = 0; it < 8; it++) {
        int idx4 = tid + it * 256;
        int r = idx4 >> 5;                     // 0..63
        int c = (idx4 & 31) * 4;               // 0..124
        float4 v = make_float4(0.f, 0.f, 0.f, 0.f);
        if (row0 + r < n) v = *(const float4*)(d_h + (row0 + r) * HDIM + c);
        Ast[c][r] = v.x; Ast[c + 1][r] = v.y; Ast[c + 2][r] = v.z; Ast[c + 3][r] = v.w;
    }
    __syncthreads();
    int wid = tid >> 5, lane = tid & 31;
    int rbase = wid * 8;
    int col = lane * 4;
    int head = lane >> 3;

    // acc2[rp][c] packs rows (rbase+2rp, rbase+2rp+1) for column col+c
    unsigned long long acc2[4][4];
    #pragma unroll
    for (int rp = 0; rp < 4; rp++)
        #pragma unroll
        for (int c = 0; c < 4; c++) acc2[rp][c] = 0ull;

    #pragma unroll 8
    for (int k = 0; k < HDIM; k++) {
        unsigned long long ap[4];
        #pragma unroll
        for (int rp = 0; rp < 4; rp++)
            ap[rp] = *(const unsigned long long*)&Ast[k][rbase + 2 * rp];
        float4 b = __ldg((const float4*)(B + k * HDIM + col));
        unsigned long long bd[4];
        PACK_DUP(bd[0], b.x); PACK_DUP(bd[1], b.y);
        PACK_DUP(bd[2], b.z); PACK_DUP(bd[3], b.w);
        #pragma unroll
        for (int rp = 0; rp < 4; rp++) {
            FMA2(acc2[rp][0], ap[rp], bd[0]);
            FMA2(acc2[rp][1], ap[rp], bd[1]);
            FMA2(acc2[rp][2], ap[rp], bd[2]);
            FMA2(acc2[rp][3], ap[rp], bd[3]);
        }
    }

    // unpack to scalar accumulators
    float acc[8][4];
    #pragma unroll
    for (int rp = 0; rp < 4; rp++)
        #pragma unroll
        for (int c = 0; c < 4; c++) {
            unsigned int lo, hi;
            UNPACK2(lo, hi, acc2[rp][c]);
            acc[2 * rp][c] = __uint_as_float(lo);
            acc[2 * rp + 1][c] = __uint_as_float(hi);
        }

    float4 av = __ldg((const float4*)(al + col));
    float4 rv = __ldg((const float4*)(ar + col));
    float myelmax = -1e30f;
    #pragma unroll
    for (int r = 0; r < 8; r++) {
        int row = row0 + rbase + r;
        if (row < n) {
            float4 o = make_float4(acc[r][0], acc[r][1], acc[r][2], acc[r][3]);
            *(float4*)(d_feat + row * HDIM + col) = o;
        }
        float sl = acc[r][0] * av.x + acc[r][1] * av.y + acc[r][2] * av.z + acc[r][3] * av.w;
        float sr = acc[r][0] * rv.x + acc[r][1] * rv.y + acc[r][2] * rv.z + acc[r][3] * rv.w;
        #pragma unroll
        for (int o = 4; o > 0; o >>= 1) {
            sl += __shfl_xor_sync(0xffffffffu, sl, o);
            sr += __shfl_xor_sync(0xffffffffu, sr, o);
        }
        if ((lane & 7) == 0 && row < n) {
            d_el[row * NHEADS + head] = sl;
            d_er[row * NHEADS + head] = sr;
            myelmax = fmaxf(myelmax, sl);
        }
    }
    if ((lane & 7) == 0) atomicMaxFloat(&smax[head], myelmax);
    __syncthreads();
    if (tid < NHEADS) atomicMaxFloat(&d_elmax[l * NHEADS + tid], smax[tid]);
}

// Fused per-layer GAT aggregation: warp per dst node. Single edge pass:
// m_h = leaky(global_el_max_h + er_h) is a valid softmax shift (monotone bound).
__global__ void gat_fused_k(const float* __restrict__ bias, int n, int l) {
    __shared__ float sh_a[8][128];   // per warp: 32 edges x 4 heads
    int warp = (blockIdx.x * blockDim.x + threadIdx.x) >> 5;
    if (warp >= n) return;
    int w = threadIdx.x >> 5;
    int lane = threadIdx.x & 31;
    int node = warp;
    int rs = d_offs[node], re = d_offs[node + 1];
    int head = lane >> 3;

    float4 er4 = *(const float4*)(d_er + node * NHEADS);
    float4 em = *(const float4*)(d_elmax + l * NHEADS);
    float m[4];
    {
        float t0 = em.x + er4.x; m[0] = (t0 > 0.0f) ? t0 : 0.2f * t0;
        float t1 = em.y + er4.y; m[1] = (t1 > 0.0f) ? t1 : 0.2f * t1;
        float t2 = em.z + er4.z; m[2] = (t2 > 0.0f) ? t2 : 0.2f * t2;
        float t3 = em.w + er4.w; m[3] = (t3 > 0.0f) ? t3 : 0.2f * t3;
    }

    float4 zacc = make_float4(0.0f, 0.0f, 0.0f, 0.0f);
    float4 acc = make_float4(0.0f, 0.0f, 0.0f, 0.0f);
    for (int base = rs; base < re; base += 32) {
        int i = base + lane;
        int s_reg = 0;
        float4 a4 = make_float4(0.0f, 0.0f, 0.0f, 0.0f);
        if (i < re) {
            s_reg = d_esrc[i];
            float4 el4 = *(const float4*)(d_el + s_reg * NHEADS);
            float v0 = el4.x + er4.x; v0 = (v0 > 0.0f) ? v0 : 0.2f * v0;
            float v1 = el4.y + er4.y; v1 = (v1 > 0.0f) ? v1 : 0.2f * v1;
            float v2 = el4.z + er4.z; v2 = (v2 > 0.0f) ? v2 : 0.2f * v2;
            float v3 = el4.w + er4.w; v3 = (v3 > 0.0f) ? v3 : 0.2f * v3;
            a4.x = __expf(v0 - m[0]); a4.y = __expf(v1 - m[1]);
            a4.z = __expf(v2 - m[2]); a4.w = __expf(v3 - m[3]);
            zacc.x += a4.x; zacc.y += a4.y; zacc.z += a4.z; zacc.w += a4.w;
        }
        *(float4*)&sh_a[w][lane * 4] = a4;
        __syncwarp();
        int cnt = min(32, re - base);
        #pragma unroll 4
        for (int j = 0; j < cnt; j++) {
            int s = __shfl_sync(0xffffffffu, s_reg, j);
            float a = sh_a[w][j * 4 + head];
            float4 f = *(const float4*)(d_feat + s * HDIM + lane * 4);
            acc.x += a * f.x; acc.y += a * f.y; acc.z += a * f.z; acc.w += a * f.w;
        }
        __syncwarp();
    }
    #pragma unroll
    for (int o = 16; o > 0; o >>= 1) {
        zacc.x += __shfl_xor_sync(0xffffffffu, zacc.x, o);
        zacc.y += __shfl_xor_sync(0xffffffffu, zacc.y, o);
        zacc.z += __shfl_xor_sync(0xffffffffu, zacc.z, o);
        zacc.w += __shfl_xor_sync(0xffffffffu, zacc.w, o);
    }
    float zh[4] = {zacc.x, zacc.y, zacc.z, zacc.w};
    float zq = zh[head];
    float rz = (zq > 0.0f) ? (1.0f / zq) : 0.0f;

    float4 hv = *(const float4*)(d_h + node * HDIM + lane * 4);
    float4 bv = *(const float4*)(bias + lane * 4);
    float4 y;
    y.x = fmaxf(acc.x * rz + hv.x + bv.x, 0.0f);
    y.y = fmaxf(acc.y * rz + hv.y + bv.y, 0.0f);
    y.z = fmaxf(acc.z * rz + hv.z + bv.z, 0.0f);
    y.w = fmaxf(acc.w * rz + hv.w + bv.w, 0.0f);
    *(float4*)(d_h + node * HDIM + lane * 4) = y;
}

// Fused LayerNorm + gate projection + per-graph gate max.
__global__ void ln_gate_k(const float* __restrict__ gamma, const float* __restrict__ beta,
                          const float* __restrict__ gw, const float* __restrict__ gb,
                          const int* __restrict__ gid, int n) {
    int t = blockIdx.x * blockDim.x + threadIdx.x;
    int node = t >> 5;
    if (node >= n) return;
    int lane = t & 31;
    float4 x = *(const float4*)(d_h + node * HDIM + lane * 4);
    float s = x.x + x.y + x.z + x.w;
    float sq = x.x * x.x + x.y * x.y + x.z * x.z + x.w * x.w;
    s = warpSum(s);
    sq = warpSum(sq);
    float mu = s * (1.0f / HDIM);
    float var = sq * (1.0f / HDIM) - mu * mu;
    float inv = rsqrtf(var + 1e-5f);
    float4 g = *(const float4*)(gamma + lane * 4);
    float4 b = *(const float4*)(beta + lane * 4);
    float4 y;
    y.x = (x.x - mu) * inv * g.x + b.x;
    y.y = (x.y - mu) * inv * g.y + b.y;
    y.z = (x.z - mu) * inv * g.z + b.z;
    y.w = (x.w - mu) * inv * g.w + b.w;
    *(float4*)(d_h + node * HDIM + lane * 4) = y;
    float4 w = *(const float4*)(gw + lane * 4);
    float gp = y.x * w.x + y.y * w.y + y.z * w.z + y.w * w.w;
    gp = warpSum(gp);
    if (lane == 0) {
        float gv = gp + gb[0];
        d_gate[node] = gv;
        atomicMaxFloat(&d_gmax[gid[node]], gv);
    }
}

__global__ void pool_init_k() {
    int i = blockIdx.x * blockDim.x + threadIdx.x;
    if (i < GMAX * HDIM) d_zg[i] = 0.0f;
    if (i < GMAX) { d_gmax[i] = -INFINITY; d_gz[i] = 0.0f; }
}

// pool: p = exp(gate - gmax); gz += p; zg += p*h. One warp per node.
__global__ void pool_k(const int* __restrict__ gid, int n) {
    int t = blockIdx.x * blockDim.x + threadIdx.x;
    int node = t >> 5;
    if (node >= n) return;
    int lane = t & 31;
    int g = gid[node];
    float p = __expf(d_gate[node] - d_gmax[g]);
    if (lane == 0) atomicAdd(&d_gz[g], p);
    float4 x = *(const float4*)(d_h + node * HDIM + lane * 4);
    redAdd4(d_zg + g * HDIM + lane * 4, x.x * p, x.y * p, x.z * p, x.w * p);
}

// z1 = relu((zg/gz) @ proj_w1 + b1)
__global__ void final1_k(const float* __restrict__ W1, const float* __restrict__ b1) {
    __shared__ float row[HDIM];
    int g = blockIdx.x;
    int t = threadIdx.x;
    float gz = d_gz[g];
    float inv = (gz > 0.0f) ? (1.0f / gz) : 0.0f;
    row[t] = d_zg[g * HDIM + t] * inv;
    __syncthreads();
    float acc = b1[t];
    #pragma unroll 8
    for (int k = 0; k < HDIM; k++) acc += row[k] * W1[k * HDIM + t];
    d_z1[g * HDIM + t] = (acc > 0.0f) ? acc : 0.0f;
}

// out = z1 @ proj_w2 + b2
__global__ void final2_k(const float* __restrict__ W2, const float* __restrict__ b2,
                         float* __restrict__ out) {
    __shared__ float row[HDIM];
    int g = blockIdx.x;
    int t = threadIdx.x;
    row[t] = d_z1[g * HDIM + t];
    row[t + 64] = d_z1[g * HDIM + t + 64];
    __syncthreads();
    float acc = b2[t];
    #pragma unroll 8
    for (int k = 0; k < HDIM; k++) acc += row[k] * W2[k * 64 + t];
    out[g * 64 + t] = acc;
}

// ---------------- launch ----------------
extern "C" void kernel_launch(void* const* d_in, const int* in_sizes, int n_in,
                              void* d_out, int out_size) {
    const int*   gt    = (const int*)d_in[0];
    const int*   qi    = (const int*)d_in[1];
    const int*   src   = (const int*)d_in[2];
    const int*   dst   = (const int*)d_in[3];
    const int*   gid   = (const int*)d_in[4];
    const float* ge    = (const float*)d_in[5];
    const float* qe    = (const float*)d_in[6];
    const float* W     = (const float*)d_in[7];
    const float* al    = (const float*)d_in[8];
    const float* ar    = (const float*)d_in[9];
    const float* bias  = (const float*)d_in[10];
    const float* gamma = (const float*)d_in[11];
    const float* beta  = (const float*)d_in[12];
    const float* gw    = (const float*)d_in[13];
    const float* gb    = (const float*)d_in[14];
    const float* W1    = (const float*)d_in[15];
    const float* b1    = (const float*)d_in[16];
    const float* W2    = (const float*)d_in[17];
    const float* b2    = (const float*)d_in[18];

    int n = in_sizes[0];
    int e = in_sizes[2];

    const int T = 256;
    int gEmbed = (n * (HDIM / 4) + T - 1) / T;
    int gGemm  = (n + 63) / 64;
    int gWarpN = (n * 32 + T - 1) / T;
    int gEdge  = (e + T - 1) / T;
    int gNode  = (n + T - 1) / T;
    int nb     = (n + 1023) / 1024;

    embed_k<<<gEmbed, T>>>(gt, qi, ge, qe, n);

    csr_zero_k<<<gNode, T>>>(n);
    csr_hist_k<<<gEdge, T>>>(dst, e);
    csr_scan1_k<<<nb, 1024>>>(n);
    csr_scan2_k<<<1, 32>>>(nb, n);
    csr_scan3_k<<<nb, 1024>>>(n);
    csr_scatter_k<<<gEdge, T>>>(src, dst, e);

    for (int l = 0; l < 3; l++) {
        gemm_attn_k<<<gGemm, 256>>>(W + l * HDIM * HDIM, al + l * HDIM, ar + l * HDIM, n, l);
        gat_fused_k<<<gWarpN, T>>>(bias + l * HDIM, n, l);
    }

    pool_init_k<<<(GMAX * HDIM + T - 1) / T, T>>>();
    ln_gate_k<<<gWarpN, T>>>(gamma, beta, gw, gb, gid, n);
    pool_k<<<gWarpN, T>>>(gid, n);
    final1_k<<<GMAX, HDIM>>>(W1, b1);
    final2_k<<<GMAX, 64>>>(W2, b2, (float*)d_out);
}

// round 8
// speedup vs baseline: 1.1123x; 1.0890x over previous
#include <cuda_runtime.h>
#include <math.h>

#define NMAX 50000
#define EMAX 600000
#define HDIM 128
#define NHEADS 4
#define GMAX 64

// ---------------- scratch (device globals; no allocation) ----------------
__device__ float d_h[NMAX * HDIM];
__device__ float d_feat[NMAX * HDIM];
__device__ float d_el[NMAX * NHEADS];
__device__ float d_er[NMAX * NHEADS];
__device__ float d_elmax[3 * NHEADS];      // per-layer, per-head global max of el
__device__ int   d_deg[NMAX];
__device__ int   d_cur[NMAX];
__device__ int   d_offs[NMAX + 1];
__device__ int   d_esrc[EMAX];
__device__ int   d_bsum[64];
__device__ int   d_bbase[64];
__device__ float d_gz[GMAX];
__device__ float d_zg[GMAX * HDIM];

// ---------------- helpers ----------------
__device__ __forceinline__ void atomicMaxFloat(float* addr, float v) {
    if (v >= 0.0f) atomicMax((int*)addr, __float_as_int(v));
    else           atomicMin((unsigned int*)addr, __float_as_uint(v));
}

__device__ __forceinline__ void redAdd4(float* p, float a, float b, float c, float d) {
    asm volatile("red.global.add.v4.f32 [%0], {%1, %2, %3, %4};"
                 :: "l"(p), "f"(a), "f"(b), "f"(c), "f"(d) : "memory");
}

__device__ __forceinline__ float warpSum(float v) {
    #pragma unroll
    for (int o = 16; o > 0; o >>= 1) v += __shfl_xor_sync(0xffffffffu, v, o);
    return v;
}

// packed fp32x2 FMA (Blackwell): d = a*b + d elementwise on 2-lane packs
#define FMA2(d, a, b) asm("fma.rn.f32x2 %0, %1, %2, %0;" : "+l"(d) : "l"(a), "l"(b))
#define PACK_DUP(d, x) asm("mov.b64 %0, {%1, %1};" : "=l"(d) : "r"(__float_as_uint(x)))
#define UNPACK2(lo, hi, v) asm("mov.b64 {%0, %1}, %2;" : "=r"(lo), "=r"(hi) : "l"(v))

// ---------------- kernels ----------------

// --------- CSR build + global init (once per call) ---------
__global__ void csr_zero_k(int n) {
    int i = blockIdx.x * blockDim.x + threadIdx.x;
    if (i < n) { d_deg[i] = 0; d_cur[i] = 0; }
    if (i < 3 * NHEADS) d_elmax[i] = -1e30f;
    if (i < GMAX * HDIM) d_zg[i] = 0.0f;
    if (i < GMAX) d_gz[i] = 0.0f;
}

__global__ void csr_hist_k(const int* __restrict__ dst, int e) {
    int i = blockIdx.x * blockDim.x + threadIdx.x;
    if (i < e) atomicAdd(&d_deg[dst[i]], 1);
}

// phase 1: per-block (1024 elems) exclusive scan; block total -> d_bsum
__global__ void csr_scan1_k(int n) {
    __shared__ int wsum[32];
    int i = blockIdx.x * 1024 + threadIdx.x;
    int lane = threadIdx.x & 31, wid = threadIdx.x >> 5;
    int v = (i < n) ? d_deg[i] : 0;
    int x = v;
    #pragma unroll
    for (int o = 1; o < 32; o <<= 1) {
        int t = __shfl_up_sync(0xffffffffu, x, o);
        if (lane >= o) x += t;
    }
    if (lane == 31) wsum[wid] = x;
    __syncthreads();
    if (wid == 0) {
        int y = wsum[lane];
        #pragma unroll
        for (int o = 1; o < 32; o <<= 1) {
            int t = __shfl_up_sync(0xffffffffu, y, o);
            if (lane >= o) y += t;
        }
        wsum[lane] = y;
    }
    __syncthreads();
    int base = (wid > 0) ? wsum[wid - 1] : 0;
    if (i < n) d_offs[i] = base + x - v;
    if (threadIdx.x == 1023) d_bsum[blockIdx.x] = wsum[31];
}

// phase 2: one warp scans <=64 block sums exclusively; writes total to d_offs[n]
__global__ void csr_scan2_k(int nb, int n) {
    int lane = threadIdx.x;
    int v0 = (lane < nb) ? d_bsum[lane] : 0;
    int v1 = (32 + lane < nb) ? d_bsum[32 + lane] : 0;
    int x0 = v0, x1 = v1;
    #pragma unroll
    for (int o = 1; o < 32; o <<= 1) {
        int t0 = __shfl_up_sync(0xffffffffu, x0, o);
        int t1 = __shfl_up_sync(0xffffffffu, x1, o);
        if (lane >= o) { x0 += t0; x1 += t1; }
    }
    int tot0 = __shfl_sync(0xffffffffu, x0, 31);
    int tot1 = __shfl_sync(0xffffffffu, x1, 31);
    if (lane < nb) d_bbase[lane] = x0 - v0;
    if (32 + lane < nb) d_bbase[32 + lane] = tot0 + x1 - v1;
    if (lane == 0) d_offs[n] = tot0 + tot1;
}

// phase 3: add block bases
__global__ void csr_scan3_k(int n) {
    int i = blockIdx.x * 1024 + threadIdx.x;
    if (i < n) d_offs[i] += d_bbase[blockIdx.x];
}

__global__ void csr_scatter_k(const int* __restrict__ src, const int* __restrict__ dst, int e) {
    int i = blockIdx.x * blockDim.x + threadIdx.x;
    if (i >= e) return;
    int d = dst[i];
    int pos = d_offs[d] + atomicAdd(&d_cur[d], 1);
    d_esrc[pos] = src[i];
}

// feat = h @ W[l] with fused attn epilogue + per-head global el-max.
// For l==0 (gt != nullptr) the embedding h = ge[gt]+qe[qi] is computed in the
// staging loop and also written to d_h (replaces the separate embed kernel).
__global__ void gemm_attn_k(const float* __restrict__ B,
                            const float* __restrict__ al, const float* __restrict__ ar,
                            int n, int l,
                            const int* __restrict__ gt, const int* __restrict__ qi,
                            const float* __restrict__ ge, const float* __restrict__ qe) {
    __shared__ float Ast[HDIM][68];
    __shared__ float smax[NHEADS];
    int row0 = blockIdx.x * 64;
    int tid = threadIdx.x;
    if (tid < NHEADS) smax[tid] = -1e30f;
    #pragma unroll
    for (int it = 0; it < 8; it++) {
        int idx4 = tid + it * 256;
        int r = idx4 >> 5;                     // 0..63
        int c = (idx4 & 31) * 4;               // 0..124
        int row = row0 + r;
        float4 v = make_float4(0.f, 0.f, 0.f, 0.f);
        if (row < n) {
            if (gt) {
                int gg = gt[row], qq = qi[row];
                float4 a = *(const float4*)(ge + gg * HDIM + c);
                float4 b = *(const float4*)(qe + qq * HDIM + c);
                v.x = a.x + b.x; v.y = a.y + b.y; v.z = a.z + b.z; v.w = a.w + b.w;
                *(float4*)(d_h + row * HDIM + c) = v;
            } else {
                v = *(const float4*)(d_h + row * HDIM + c);
            }
        }
        Ast[c][r] = v.x; Ast[c + 1][r] = v.y; Ast[c + 2][r] = v.z; Ast[c + 3][r] = v.w;
    }
    __syncthreads();
    int wid = tid >> 5, lane = tid & 31;
    int rbase = wid * 8;
    int col = lane * 4;
    int head = lane >> 3;

    unsigned long long acc2[4][4];
    #pragma unroll
    for (int rp = 0; rp < 4; rp++)
        #pragma unroll
        for (int c = 0; c < 4; c++) acc2[rp][c] = 0ull;

    #pragma unroll 8
    for (int k = 0; k < HDIM; k++) {
        unsigned long long ap[4];
        #pragma unroll
        for (int rp = 0; rp < 4; rp++)
            ap[rp] = *(const unsigned long long*)&Ast[k][rbase + 2 * rp];
        float4 b = __ldg((const float4*)(B + k * HDIM + col));
        unsigned long long bd[4];
        PACK_DUP(bd[0], b.x); PACK_DUP(bd[1], b.y);
        PACK_DUP(bd[2], b.z); PACK_DUP(bd[3], b.w);
        #pragma unroll
        for (int rp = 0; rp < 4; rp++) {
            FMA2(acc2[rp][0], ap[rp], bd[0]);
            FMA2(acc2[rp][1], ap[rp], bd[1]);
            FMA2(acc2[rp][2], ap[rp], bd[2]);
            FMA2(acc2[rp][3], ap[rp], bd[3]);
        }
    }

    float acc[8][4];
    #pragma unroll
    for (int rp = 0; rp < 4; rp++)
        #pragma unroll
        for (int c = 0; c < 4; c++) {
            unsigned int lo, hi;
            UNPACK2(lo, hi, acc2[rp][c]);
            acc[2 * rp][c] = __uint_as_float(lo);
            acc[2 * rp + 1][c] = __uint_as_float(hi);
        }

    float4 av = __ldg((const float4*)(al + col));
    float4 rv = __ldg((const float4*)(ar + col));
    float myelmax = -1e30f;
    #pragma unroll
    for (int r = 0; r < 8; r++) {
        int row = row0 + rbase + r;
        if (row < n) {
            float4 o = make_float4(acc[r][0], acc[r][1], acc[r][2], acc[r][3]);
            *(float4*)(d_feat + row * HDIM + col) = o;
        }
        float sl = acc[r][0] * av.x + acc[r][1] * av.y + acc[r][2] * av.z + acc[r][3] * av.w;
        float sr = acc[r][0] * rv.x + acc[r][1] * rv.y + acc[r][2] * rv.z + acc[r][3] * rv.w;
        #pragma unroll
        for (int o = 4; o > 0; o >>= 1) {
            sl += __shfl_xor_sync(0xffffffffu, sl, o);
            sr += __shfl_xor_sync(0xffffffffu, sr, o);
        }
        if ((lane & 7) == 0 && row < n) {
            d_el[row * NHEADS + head] = sl;
            d_er[row * NHEADS + head] = sr;
            myelmax = fmaxf(myelmax, sl);
        }
    }
    if ((lane & 7) == 0) atomicMaxFloat(&smax[head], myelmax);
    __syncthreads();
    if (tid < NHEADS) atomicMaxFloat(&d_elmax[l * NHEADS + tid], smax[tid]);
}

// Fused per-layer GAT aggregation: warp per dst node. Single edge pass.
// z (softmax denominator) is accumulated FOR FREE in the gather loop (every
// lane reads a anyway), so no cross-warp reduction is needed.
__global__ void gat_fused_k(const float* __restrict__ bias, int n, int l) {
    __shared__ float sh_a[8][128];   // per warp: 32 edges x 4 heads
    int warp = (blockIdx.x * blockDim.x + threadIdx.x) >> 5;
    if (warp >= n) return;
    int w = threadIdx.x >> 5;
    int lane = threadIdx.x & 31;
    int node = warp;
    int rs = d_offs[node], re = d_offs[node + 1];
    int head = lane >> 3;

    float4 er4 = *(const float4*)(d_er + node * NHEADS);
    float4 em = *(const float4*)(d_elmax + l * NHEADS);
    float m[4];
    {
        float t0 = em.x + er4.x; m[0] = (t0 > 0.0f) ? t0 : 0.2f * t0;
        float t1 = em.y + er4.y; m[1] = (t1 > 0.0f) ? t1 : 0.2f * t1;
        float t2 = em.z + er4.z; m[2] = (t2 > 0.0f) ? t2 : 0.2f * t2;
        float t3 = em.w + er4.w; m[3] = (t3 > 0.0f) ? t3 : 0.2f * t3;
    }

    float z = 0.0f;
    float4 acc = make_float4(0.0f, 0.0f, 0.0f, 0.0f);
    for (int base = rs; base < re; base += 32) {
        int i = base + lane;
        int s_reg = 0;
        float4 a4 = make_float4(0.0f, 0.0f, 0.0f, 0.0f);
        if (i < re) {
            s_reg = d_esrc[i];
            float4 el4 = *(const float4*)(d_el + s_reg * NHEADS);
            float v0 = el4.x + er4.x; v0 = (v0 > 0.0f) ? v0 : 0.2f * v0;
            float v1 = el4.y + er4.y; v1 = (v1 > 0.0f) ? v1 : 0.2f * v1;
            float v2 = el4.z + er4.z; v2 = (v2 > 0.0f) ? v2 : 0.2f * v2;
            float v3 = el4.w + er4.w; v3 = (v3 > 0.0f) ? v3 : 0.2f * v3;
            a4.x = __expf(v0 - m[0]); a4.y = __expf(v1 - m[1]);
            a4.z = __expf(v2 - m[2]); a4.w = __expf(v3 - m[3]);
        }
        *(float4*)&sh_a[w][lane * 4] = a4;
        __syncwarp();
        int cnt = min(32, re - base);
        #pragma unroll 4
        for (int j = 0; j < cnt; j++) {
            int s = __shfl_sync(0xffffffffu, s_reg, j);
            float a = sh_a[w][j * 4 + head];
            z += a;                                   // free denominator
            float4 f = *(const float4*)(d_feat + s * HDIM + lane * 4);
            acc.x += a * f.x; acc.y += a * f.y; acc.z += a * f.z; acc.w += a * f.w;
        }
        __syncwarp();
    }
    float rz = (z > 0.0f) ? (1.0f / z) : 0.0f;

    float4 hv = *(const float4*)(d_h + node * HDIM + lane * 4);
    float4 bv = *(const float4*)(bias + lane * 4);
    float4 y;
    y.x = fmaxf(acc.x * rz + hv.x + bv.x, 0.0f);
    y.y = fmaxf(acc.y * rz + hv.y + bv.y, 0.0f);
    y.z = fmaxf(acc.z * rz + hv.z + bv.z, 0.0f);
    y.w = fmaxf(acc.w * rz + hv.w + bv.w, 0.0f);
    *(float4*)(d_h + node * HDIM + lane * 4) = y;
}

// Fused LayerNorm + gate + pooling accumulation (shift-0 softmax: LN bounds
// |gate| to a few units, so exp() is safe and per-graph ratios are exact).
__global__ void ln_gate_pool_k(const float* __restrict__ gamma, const float* __restrict__ beta,
                               const float* __restrict__ gw, const float* __restrict__ gb,
                               const int* __restrict__ gid, int n) {
    int t = blockIdx.x * blockDim.x + threadIdx.x;
    int node = t >> 5;
    if (node >= n) return;
    int lane = t & 31;
    float4 x = *(const float4*)(d_h + node * HDIM + lane * 4);
    float s = x.x + x.y + x.z + x.w;
    float sq = x.x * x.x + x.y * x.y + x.z * x.z + x.w * x.w;
    s = warpSum(s);
    sq = warpSum(sq);
    float mu = s * (1.0f / HDIM);
    float var = sq * (1.0f / HDIM) - mu * mu;
    float inv = rsqrtf(var + 1e-5f);
    float4 g = *(const float4*)(gamma + lane * 4);
    float4 b = *(const float4*)(beta + lane * 4);
    float4 y;
    y.x = (x.x - mu) * inv * g.x + b.x;
    y.y = (x.y - mu) * inv * g.y + b.y;
    y.z = (x.z - mu) * inv * g.z + b.z;
    y.w = (x.w - mu) * inv * g.w + b.w;
    float4 w = *(const float4*)(gw + lane * 4);
    float gp = y.x * w.x + y.y * w.y + y.z * w.z + y.w * w.w;
    gp = warpSum(gp);
    float p = __expf(gp + gb[0]);
    int gr = gid[node];
    if (lane == 0) atomicAdd(&d_gz[gr], p);
    redAdd4(d_zg + gr * HDIM + lane * 4, p * y.x, p * y.y, p * y.z, p * y.w);
}

// out = relu((zg/gz) @ W1 + b1) @ W2 + b2, one block per graph
__global__ void final_k(const float* __restrict__ W1, const float* __restrict__ b1,
                        const float* __restrict__ W2, const float* __restrict__ b2,
                        float* __restrict__ out) {
    __shared__ float row[HDIM];
    __shared__ float z1[HDIM];
    int g = blockIdx.x;
    int t = threadIdx.x;
    float gz = d_gz[g];
    float inv = (gz > 0.0f) ? (1.0f / gz) : 0.0f;
    row[t] = d_zg[g * HDIM + t] * inv;
    __syncthreads();
    float acc = b1[t];
    #pragma unroll 8
    for (int k = 0; k < HDIM; k++) acc += row[k] * W1[k * HDIM + t];
    z1[t] = (acc > 0.0f) ? acc : 0.0f;
    __syncthreads();
    if (t < 64) {
        float a2 = b2[t];
        #pragma unroll 8
        for (int k = 0; k < HDIM; k++) a2 += z1[k] * W2[k * 64 + t];
        out[g * 64 + t] = a2;
    }
}

// ---------------- launch ----------------
extern "C" void kernel_launch(void* const* d_in, const int* in_sizes, int n_in,
                              void* d_out, int out_size) {
    const int*   gt    = (const int*)d_in[0];
    const int*   qi    = (const int*)d_in[1];
    const int*   src   = (const int*)d_in[2];
    const int*   dst   = (const int*)d_in[3];
    const int*   gid   = (const int*)d_in[4];
    const float* ge    = (const float*)d_in[5];
    const float* qe    = (const float*)d_in[6];
    const float* W     = (const float*)d_in[7];
    const float* al    = (const float*)d_in[8];
    const float* ar    = (const float*)d_in[9];
    const float* bias  = (const float*)d_in[10];
    const float* gamma = (const float*)d_in[11];
    const float* beta  = (const float*)d_in[12];
    const float* gw    = (const float*)d_in[13];
    const float* gb    = (const float*)d_in[14];
    const float* W1    = (const float*)d_in[15];
    const float* b1    = (const float*)d_in[16];
    const float* W2    = (const float*)d_in[17];
    const float* b2    = (const float*)d_in[18];

    int n = in_sizes[0];
    int e = in_sizes[2];

    const int T = 256;
    int gGemm  = (n + 63) / 64;
    int gWarpN = (n * 32 + T - 1) / T;
    int gEdge  = (e + T - 1) / T;
    int gNode  = (n + T - 1) / T;
    int nb     = (n + 1023) / 1024;

    csr_zero_k<<<gNode, T>>>(n);                                   // 1
    csr_hist_k<<<gEdge, T>>>(dst, e);                              // 2
    csr_scan1_k<<<nb, 1024>>>(n);                                  // 3
    gemm_attn_k<<<gGemm, 256>>>(W, al, ar, n, 0, gt, qi, ge, qe);  // 4 (profiled)
    csr_scan2_k<<<1, 32>>>(nb, n);                                 // 5
    csr_scan3_k<<<nb, 1024>>>(n);                                  // 6
    csr_scatter_k<<<gEdge, T>>>(src, dst, e);                      // 7
    gat_fused_k<<<gWarpN, T>>>(bias, n, 0);                        // 8

    for (int l = 1; l < 3; l++) {
        gemm_attn_k<<<gGemm, 256>>>(W + l * HDIM * HDIM, al + l * HDIM, ar + l * HDIM,
                                    n, l, nullptr, nullptr, nullptr, nullptr);
        gat_fused_k<<<gWarpN, T>>>(bias + l * HDIM, n, l);
    }

    ln_gate_pool_k<<<gWarpN, T>>>(gamma, beta, gw, gb, gid, n);
    final_k<<<GMAX, HDIM>>>(W1, b1, W2, b2, (float*)d_out);
}